// round 17
// baseline (speedup 1.0000x reference)
#include <cuda_runtime.h>
#include <cuda_fp16.h>
#include <cstdint>
#include <math.h>

#define BSZ 64
#define TSZ 512
#define ESZ 256
#define USZ 512
#define GSZ 2048
#define NBLK 128
#define FANIN 16

// xz layout: [dir][r = t*64+b][gc = u*4+g]
__device__ float  g_xz[(size_t)2 * TSZ * BSZ * GSZ];
__device__ __half g_hf[2][2][(size_t)BSZ * USZ];          // fallback path only
__device__ unsigned g_bar_cnt[256];                       // fallback path only

// ---- helpers ----
__device__ __forceinline__ uint32_t s2u(const void* p) {
    uint32_t a; asm("{.reg .u64 t; cvta.to.shared.u64 t, %1; cvt.u32.u64 %0, t;}" : "=r"(a) : "l"(p));
    return a;
}
__device__ __forceinline__ uint32_t ctarank() {
    uint32_t r; asm("mov.u32 %0, %%cluster_ctarank;" : "=r"(r)); return r;
}
__device__ __forceinline__ void ldsm4(uint32_t& r0, uint32_t& r1, uint32_t& r2, uint32_t& r3, uint32_t a) {
    asm volatile("ldmatrix.sync.aligned.m8n8.x4.shared.b16 {%0,%1,%2,%3}, [%4];"
                 : "=r"(r0), "=r"(r1), "=r"(r2), "=r"(r3) : "r"(a));
}
__device__ __forceinline__ void ldsm4t(uint32_t& r0, uint32_t& r1, uint32_t& r2, uint32_t& r3, uint32_t a) {
    asm volatile("ldmatrix.sync.aligned.m8n8.x4.trans.shared.b16 {%0,%1,%2,%3}, [%4];"
                 : "=r"(r0), "=r"(r1), "=r"(r2), "=r"(r3) : "r"(a));
}
__device__ __forceinline__ void mma16816(float* c, uint32_t a0, uint32_t a1, uint32_t a2, uint32_t a3,
                                         uint32_t b0, uint32_t b1) {
    asm volatile("mma.sync.aligned.m16n8k16.row.col.f32.f16.f16.f32 "
                 "{%0,%1,%2,%3}, {%4,%5,%6,%7}, {%8,%9}, {%0,%1,%2,%3};"
                 : "+f"(c[0]), "+f"(c[1]), "+f"(c[2]), "+f"(c[3])
                 : "r"(a0), "r"(a1), "r"(a2), "r"(a3), "r"(b0), "r"(b1));
}
__device__ __forceinline__ float sigf(float x) { return __fdividef(1.f, 1.f + __expf(-x)); }
__device__ __forceinline__ float tanhf_(float x) { return __fdividef(2.f, 1.f + __expf(-2.f * x)) - 1.f; }

__global__ void reset_bar_kernel() {
    g_bar_cnt[threadIdx.x] = 0u;
}

// ---------------------------------------------------------------------------
// Kernel 1: HMMA GEMM.  xz[r][gc] = emb[idx] @ W (+bias), fp16 in, fp32 out.
// ---------------------------------------------------------------------------
#define G1_AS 0
#define G1_BS 67584
#define G1_SMEM (67584 + 69632)

__global__ void __launch_bounds__(256) xz_gemm_hmma(
    const int* __restrict__ idx, const float* __restrict__ emb,
    const float* __restrict__ Wf, const float* __restrict__ bf,
    const float* __restrict__ Wb, const float* __restrict__ bb)
{
    extern __shared__ char sm[];
    __shared__ int rowv[128];

    const int dir = blockIdx.z;
    const float* __restrict__ W    = dir ? Wb : Wf;
    const float* __restrict__ bias = dir ? bb : bf;
    float* __restrict__ xzd = g_xz + (size_t)dir * TSZ * BSZ * GSZ;

    const int tid    = threadIdx.x;
    const int rbase  = blockIdx.y * 128;
    const int gcbase = blockIdx.x * 128;
    const int ubase  = gcbase >> 2;

    if (tid < 128) {
        int r = rbase + tid;
        rowv[tid] = idx[(r & 63) * TSZ + (r >> 6)];
    }
    __syncthreads();

    {
        const int lm = tid >> 1, hf = tid & 1;
        const float* ar = emb + (size_t)rowv[lm] * ESZ + hf * 128;
        char* dst = sm + G1_AS + lm * 528 + hf * 256;
#pragma unroll
        for (int j = 0; j < 32; ++j) {
            float4 v = ((const float4*)ar)[j];
            __half2 h01 = __float22half2_rn(make_float2(v.x, v.y));
            __half2 h23 = __float22half2_rn(make_float2(v.z, v.w));
            *(__half2*)(dst + j * 8)     = h01;
            *(__half2*)(dst + j * 8 + 4) = h23;
        }
    }
    {
        const int k = tid;
        const float* wr = W + (size_t)k * GSZ;
        char* dst = sm + G1_BS + k * 272;
#pragma unroll
        for (int gp = 0; gp < 2; ++gp) {
#pragma unroll
            for (int uq = 0; uq < 8; ++uq) {
                float4 va = *(const float4*)&wr[(2 * gp) * USZ + ubase + uq * 4];
                float4 vb = *(const float4*)&wr[(2 * gp + 1) * USZ + ubase + uq * 4];
                const float* pa = (const float*)&va;
                const float* pb = (const float*)&vb;
#pragma unroll
                for (int i = 0; i < 4; ++i) {
                    __half2 hv = __float22half2_rn(make_float2(pa[i], pb[i]));
                    *(__half2*)(dst + ((uq * 4 + i) * 4 + 2 * gp) * 2) = hv;
                }
            }
        }
    }
    __syncthreads();

    const int w = tid >> 5, l = tid & 31;
    const int mrow = (w & 3) * 32;
    const int ncol = (w >> 2) * 64;
    const uint32_t aB = s2u(sm) + G1_AS + (uint32_t)(mrow + (l & 15)) * 528u + (uint32_t)((l >> 4) * 8) * 2u;
    const uint32_t bB = s2u(sm) + G1_BS + (uint32_t)(l & 15) * 272u + (uint32_t)(ncol + (l >> 4) * 8) * 2u;

    float c[2][8][4];
#pragma unroll
    for (int m = 0; m < 2; ++m)
#pragma unroll
        for (int j = 0; j < 8; ++j)
#pragma unroll
            for (int q = 0; q < 4; ++q) c[m][j][q] = 0.f;

#pragma unroll 4
    for (int k16 = 0; k16 < 16; ++k16) {
        uint32_t a0, a1, a2, a3, a4, a5, a6, a7;
        ldsm4(a0, a1, a2, a3, aB + (uint32_t)k16 * 32u);
        ldsm4(a4, a5, a6, a7, aB + 16u * 528u + (uint32_t)k16 * 32u);
#pragma unroll
        for (int cg = 0; cg < 4; ++cg) {
            uint32_t b0, b1, b2, b3;
            ldsm4t(b0, b1, b2, b3, bB + (uint32_t)k16 * 4352u + (uint32_t)cg * 32u);
            mma16816(c[0][cg * 2],     a0, a1, a2, a3, b0, b1);
            mma16816(c[0][cg * 2 + 1], a0, a1, a2, a3, b2, b3);
            mma16816(c[1][cg * 2],     a4, a5, a6, a7, b0, b1);
            mma16816(c[1][cg * 2 + 1], a4, a5, a6, a7, b2, b3);
        }
    }

    float bv0[8], bv1[8];
#pragma unroll
    for (int j = 0; j < 8; ++j) {
        int gcl = ncol + j * 8 + (l & 3) * 2;
        int gc = gcbase + gcl;
        int g0 = gc & 3, u0 = gc >> 2;
        bv0[j] = bias[g0 * USZ + u0];
        bv1[j] = bias[(g0 + 1) * USZ + u0];
    }
#pragma unroll
    for (int m = 0; m < 2; ++m) {
        int rl = mrow + m * 16 + (l >> 2);
        float* d0 = xzd + (size_t)(rbase + rl) * GSZ + gcbase;
        float* d1 = xzd + (size_t)(rbase + rl + 8) * GSZ + gcbase;
#pragma unroll
        for (int j = 0; j < 8; ++j) {
            int gcl = ncol + j * 8 + (l & 3) * 2;
            *(float2*)(d0 + gcl) = make_float2(c[m][j][0] + bv0[j], c[m][j][1] + bv1[j]);
            *(float2*)(d1 + gcl) = make_float2(c[m][j][2] + bv0[j], c[m][j][3] + bv1[j]);
        }
    }
}

// ===========================================================================
// Kernel 2a (primary): cluster-16 DSMEM scan.
// Cluster = sync domain (dir, bq). rank = uj. h exchanged via peer-smem
// stripes (double-buffered) + barrier.cluster; no global h, no L2 barrier.
// ===========================================================================
#define SM_MSK 0
#define SM_AH  4096                        // half [16][520]  -> 16640
#define SM_BU  (4096 + 16640)              // half [512][136] -> 139264
#define SM_HS  (4096 + 16640 + 139264)     // stripes [2][16][32] half -> 2048
#define SMEM_CL (SM_HS + 2048)             // 162048

__global__ void __launch_bounds__(256) lstm_scan_cluster(
    const int* __restrict__ idx,
    const float* __restrict__ Uf, const float* __restrict__ Ub,
    float* __restrict__ out)
{
    extern __shared__ char smem[];
    unsigned long long* msk = (unsigned long long*)(smem + SM_MSK);
    const uint32_t SB = s2u(smem);
    const uint32_t AH = SB + SM_AH;
    const uint32_t BU = SB + SM_BU;

    const int tid = threadIdx.x;
    const int dom = blockIdx.x >> 4;                  // (dir, bq)
    const int dir = dom >> 2;
    const int bq  = dom & 3;
    const int uj  = (int)ctarank();                   // 0..15 within cluster
    const float* __restrict__ Um = dir ? Ub : Uf;
    const float* __restrict__ xzd = g_xz + (size_t)dir * TSZ * BSZ * GSZ;

    // one-time: U slice -> fp16 smem [k][gc], gc = ul*4+g, row 272 B
    for (int i = tid; i < 512 * 128; i += 256) {
        int k = i >> 7, q = i & 127;
        int g = q >> 5, ul2 = q & 31;
        float v = Um[(size_t)k * GSZ + g * USZ + uj * 32 + ul2];
        *(__half*)(smem + SM_BU + k * 272 + (ul2 * 4 + g) * 2) = __float2half(v);
    }
    // one-time: masks
    for (int tt = tid * 2; tt < tid * 2 + 2; ++tt) {
        unsigned long long m = 0ull;
        for (int b = 0; b < 64; ++b)
            if (idx[b * TSZ + tt] != 0) m |= (1ull << b);
        msk[tt] = m;
    }
    // one-time: zero A tile (h0 = 0), 16640 B = 1040 uint4
    for (int i = tid; i < 1040; i += 256)
        *(uint4*)(smem + SM_AH + i * 16) = make_uint4(0u, 0u, 0u, 0u);
    __syncthreads();

    // warp MMA coordinates: M=16, warp n16 at ncol = w*16
    const int w = tid >> 5, l = tid & 31;
    const int ncol = w * 16;
    const uint32_t aBase = AH + (uint32_t)(l & 15) * 1040u + (uint32_t)((l >> 4) * 8) * 2u;
    const uint32_t bBase = BU + (uint32_t)(l & 15) * 272u + (uint32_t)(ncol + (l >> 4) * 8) * 2u;

    // owner mapping: 2 cells per thread
    const int b_own = (l >> 2) + (l & 1) * 8;         // 0..15 local batch
    const int ul0 = w * 4 + ((l >> 1) & 1);           // units ul0, ul0+2 (local)
    const int b_glob = bq * 16 + b_own;
    float c_st[2] = { 0.f, 0.f }, h_st[2] = { 0.f, 0.f };
    const bool odd = (l & 1);

    // gather coords: each thread pulls 4 rows of one 16B chunk from one peer
    const int k8 = tid & 63;                          // chunk (8 units)
    const int gpeer = k8 >> 2;
    uint32_t peerStripe;                              // peer SM_HS base (cluster addr)
    asm("mapa.shared::cluster.u32 %0, %1, %2;"
        : "=r"(peerStripe) : "r"(SB + SM_HS), "r"(gpeer));
    const uint32_t gsrc = peerStripe + (uint32_t)(k8 & 3) * 16u;
    const uint32_t gdst = AH + (uint32_t)k8 * 16u;
    const int grow0 = tid >> 6;                       // rows grow0, +4, +8, +12

    // prefetch xz for step 0
    float4 xv[2];
    {
        int t0v = dir ? (TSZ - 1) : 0;
        const float* xr = xzd + ((size_t)t0v * BSZ + b_glob) * GSZ + uj * 128;
        xv[0] = *(const float4*)(xr + ul0 * 4);
        xv[1] = *(const float4*)(xr + (ul0 + 2) * 4);
    }

    for (int s = 0; s < TSZ; ++s) {
        const int t = dir ? (TSZ - 1 - s) : s;

        // MMA: 32 k-iters, warp m16n16 (A holds h_s)
        float c0[4] = { 0.f, 0.f, 0.f, 0.f };
        float c1[4] = { 0.f, 0.f, 0.f, 0.f };
#pragma unroll 4
        for (int k0 = 0; k0 < 32; ++k0) {
            uint32_t a0, a1, a2, a3, b0r, b1r, b2r, b3r;
            ldsm4(a0, a1, a2, a3, aBase + (uint32_t)k0 * 32u);
            ldsm4t(b0r, b1r, b2r, b3r, bBase + (uint32_t)k0 * 4352u);
            mma16816(c0, a0, a1, a2, a3, b0r, b1r);
            mma16816(c1, a0, a1, a2, a3, b2r, b3r);
        }

        // epilogue in fragments; write h stripe (parity s&1) to OWN smem
        const bool mv = (msk[t] >> b_glob) & 1ull;
        float outv[2];
        {
            __half* stripe = (__half*)(smem + SM_HS + (s & 1) * 1024);
            float* cj[2] = { c0, c1 };
#pragma unroll
            for (int j = 0; j < 2; ++j) {
                float* c = cj[j];
                float s0 = __shfl_xor_sync(0xffffffffu, odd ? c[0] : c[2], 1);
                float s1 = __shfl_xor_sync(0xffffffffu, odd ? c[1] : c[3], 1);
                float zi = (odd ? s0 : c[0]) + xv[j].x;
                float zf = (odd ? s1 : c[1]) + xv[j].y;
                float zg = (odd ? c[2] : s0) + xv[j].z;
                float zo = (odd ? c[3] : s1) + xv[j].w;
                float ig = sigf(zi), fg = sigf(zf);
                float gg = tanhf_(zg), og = sigf(zo);
                float cn = fg * c_st[j] + ig * gg;
                float hn = og * tanhf_(cn);
                if (mv) { c_st[j] = cn; h_st[j] = hn; }
                outv[j] = h_st[j];
                stripe[b_own * 32 + ul0 + 2 * j] = __float2half(h_st[j]);
            }
        }

        // out stores + next xz prefetch (overlap with peers' arrivals)
        {
            float* ob = out + ((size_t)b_glob * TSZ + t) * 1024 + dir * USZ + uj * 32;
            ob[ul0]     = outv[0];
            ob[ul0 + 2] = outv[1];
        }
        if (s + 1 < TSZ) {
            int tn = dir ? (TSZ - 2 - s) : (s + 1);
            const float* xr = xzd + ((size_t)tn * BSZ + b_glob) * GSZ + uj * 128;
            xv[0] = *(const float4*)(xr + ul0 * 4);
            xv[1] = *(const float4*)(xr + (ul0 + 2) * 4);
        }

        // cluster barrier (release own stripe, acquire peers')
        asm volatile("barrier.cluster.arrive.aligned;" ::: "memory");
        asm volatile("barrier.cluster.wait.aligned;" ::: "memory");

        // gather peer stripes (parity s&1) -> A tile for step s+1
        if (s + 1 < TSZ) {
            const uint32_t src = gsrc + (uint32_t)((s & 1) * 1024);
#pragma unroll
            for (int j = 0; j < 4; ++j) {
                int r = grow0 + j * 4;
                unsigned long long v0, v1;
                asm volatile("ld.shared::cluster.b64 %0, [%1];"
                             : "=l"(v0) : "r"(src + (uint32_t)r * 64u));
                asm volatile("ld.shared::cluster.b64 %0, [%1];"
                             : "=l"(v1) : "r"(src + (uint32_t)r * 64u + 8u));
                *(unsigned long long*)(smem + SM_AH + r * 1040 + k8 * 16)     = v0;
                *(unsigned long long*)(smem + SM_AH + r * 1040 + k8 * 16 + 8) = v1;
            }
            __syncthreads();
        }
    }

    // final states
    const size_t H0 = (size_t)BSZ * TSZ * 1024;
    const size_t C0 = H0 + (size_t)BSZ * 1024;
#pragma unroll
    for (int j = 0; j < 2; ++j) {
        int u = uj * 32 + ul0 + 2 * j;
        out[H0 + (size_t)b_glob * 1024 + dir * USZ + u] = h_st[j];
        out[C0 + (size_t)b_glob * 1024 + dir * USZ + u] = c_st[j];
    }
}

// ===========================================================================
// Kernel 2b (fallback): R16 L2-barrier scan (proven 2861us path), unchanged.
// ===========================================================================
#define SMEM_FB (4096 + 16640 + 139264)    // 160000

__global__ void __launch_bounds__(256) lstm_scan_hmma(
    const int* __restrict__ idx,
    const float* __restrict__ Uf, const float* __restrict__ Ub,
    float* __restrict__ out)
{
    extern __shared__ char smem[];
    unsigned long long* msk = (unsigned long long*)(smem + SM_MSK);
    const uint32_t AH = s2u(smem) + SM_AH;
    const uint32_t BU = s2u(smem) + SM_BU;

    const int tid = threadIdx.x;
    const int dir = blockIdx.x >> 6;
    const int bq  = (blockIdx.x >> 4) & 3;
    const int uj  = blockIdx.x & 15;
    const float* __restrict__ Um = dir ? Ub : Uf;
    const float* __restrict__ xzd = g_xz + (size_t)dir * TSZ * BSZ * GSZ;
    __half* __restrict__ hbuf[2] = { g_hf[dir][0], g_hf[dir][1] };
    unsigned* const barc = &g_bar_cnt[(dir * 4 + bq) * 32];

    for (int i = tid; i < 512 * 128; i += 256) {
        int k = i >> 7, q = i & 127;
        int g = q >> 5, ul2 = q & 31;
        float v = Um[(size_t)k * GSZ + g * USZ + uj * 32 + ul2];
        *(__half*)(smem + SM_BU + k * 272 + (ul2 * 4 + g) * 2) = __float2half(v);
    }
    for (int tt = tid * 2; tt < tid * 2 + 2; ++tt) {
        unsigned long long m = 0ull;
        for (int b = 0; b < 64; ++b)
            if (idx[b * TSZ + tt] != 0) m |= (1ull << b);
        msk[tt] = m;
    }
    {
        int r = tid >> 4, u8 = (tid & 15) * 2;
        *(__half2*)&hbuf[0][(size_t)(bq * 16 + r) * USZ + uj * 32 + u8] =
            __halves2half2(__float2half(0.f), __float2half(0.f));
    }

    unsigned target = FANIN;
    __syncthreads();
    if (tid == 0) {
        __threadfence();
        atomicAdd(barc, 1u);
        volatile unsigned* vc = barc;
        while (*vc < target) { }
        __threadfence();
    }
    target += FANIN;
    __syncthreads();

    const int w = tid >> 5, l = tid & 31;
    const int ncol = w * 16;
    const uint32_t aBase = AH + (uint32_t)(l & 15) * 1040u + (uint32_t)((l >> 4) * 8) * 2u;
    const uint32_t bBase = BU + (uint32_t)(l & 15) * 272u + (uint32_t)(ncol + (l >> 4) * 8) * 2u;

    const int b_own = (l >> 2) + (l & 1) * 8;
    const int ul0 = w * 4 + ((l >> 1) & 1);
    const int b_glob = bq * 16 + b_own;
    float c_st[2] = { 0.f, 0.f }, h_st[2] = { 0.f, 0.f };
    const bool odd = (l & 1);

    float4 xv[2];
    {
        int t0v = dir ? (TSZ - 1) : 0;
        const float* xr = xzd + ((size_t)t0v * BSZ + b_glob) * GSZ + uj * 128;
        xv[0] = *(const float4*)(xr + ul0 * 4);
        xv[1] = *(const float4*)(xr + (ul0 + 2) * 4);
    }

    for (int s = 0; s < TSZ; ++s) {
        const int t = dir ? (TSZ - 1 - s) : s;
        const int cur = s & 1, nxt = cur ^ 1;

        {
            const uint4* src = (const uint4*)hbuf[cur] + (size_t)bq * 16 * 64;
#pragma unroll
            for (int j = 0; j < 4; ++j) {
                int c = j * 256 + tid;
                int r = c >> 6, k8 = c & 63;
                *(uint4*)(smem + SM_AH + r * 1040 + k8 * 16) = src[r * 64 + k8];
            }
        }
        __syncthreads();

        float c0[4] = { 0.f, 0.f, 0.f, 0.f };
        float c1[4] = { 0.f, 0.f, 0.f, 0.f };
#pragma unroll 4
        for (int k0 = 0; k0 < 32; ++k0) {
            uint32_t a0, a1, a2, a3, b0r, b1r, b2r, b3r;
            ldsm4(a0, a1, a2, a3, aBase + (uint32_t)k0 * 32u);
            ldsm4t(b0r, b1r, b2r, b3r, bBase + (uint32_t)k0 * 4352u);
            mma16816(c0, a0, a1, a2, a3, b0r, b1r);
            mma16816(c1, a0, a1, a2, a3, b2r, b3r);
        }

        const bool mv = (msk[t] >> b_glob) & 1ull;
        float outv[2];
        {
            float* cj[2] = { c0, c1 };
#pragma unroll
            for (int j = 0; j < 2; ++j) {
                float* c = cj[j];
                float s0 = __shfl_xor_sync(0xffffffffu, odd ? c[0] : c[2], 1);
                float s1 = __shfl_xor_sync(0xffffffffu, odd ? c[1] : c[3], 1);
                float zi = (odd ? s0 : c[0]) + xv[j].x;
                float zf = (odd ? s1 : c[1]) + xv[j].y;
                float zg = (odd ? c[2] : s0) + xv[j].z;
                float zo = (odd ? c[3] : s1) + xv[j].w;
                float ig = sigf(zi), fg = sigf(zf);
                float gg = tanhf_(zg), og = sigf(zo);
                float cn = fg * c_st[j] + ig * gg;
                float hn = og * tanhf_(cn);
                if (mv) { c_st[j] = cn; h_st[j] = hn; }
                outv[j] = h_st[j];
                hbuf[nxt][(size_t)b_glob * USZ + uj * 32 + ul0 + 2 * j] = __float2half(h_st[j]);
            }
        }
        __syncthreads();
        if (tid == 0) {
            __threadfence();
            atomicAdd(barc, 1u);
        }

        {
            float* ob = out + ((size_t)b_glob * TSZ + t) * 1024 + dir * USZ + uj * 32;
            ob[ul0]     = outv[0];
            ob[ul0 + 2] = outv[1];
        }
        if (s + 1 < TSZ) {
            int tn = dir ? (TSZ - 2 - s) : (s + 1);
            const float* xr = xzd + ((size_t)tn * BSZ + b_glob) * GSZ + uj * 128;
            xv[0] = *(const float4*)(xr + ul0 * 4);
            xv[1] = *(const float4*)(xr + (ul0 + 2) * 4);

            if (tid == 0) {
                volatile unsigned* vc = barc;
                while (*vc < target) { }
                __threadfence();
            }
            target += FANIN;
            __syncthreads();
        }
    }

    const size_t H0 = (size_t)BSZ * TSZ * 1024;
    const size_t C0 = H0 + (size_t)BSZ * 1024;
#pragma unroll
    for (int j = 0; j < 2; ++j) {
        int u = uj * 32 + ul0 + 2 * j;
        out[H0 + (size_t)b_glob * 1024 + dir * USZ + u] = h_st[j];
        out[C0 + (size_t)b_glob * 1024 + dir * USZ + u] = c_st[j];
    }
}

// ---------------------------------------------------------------------------
extern "C" void kernel_launch(void* const* d_in, const int* in_sizes, int n_in,
                              void* d_out, int out_size)
{
    const int*   idx = (const int*)  d_in[0];
    const float* emb = (const float*)d_in[1];
    const float* Wf  = (const float*)d_in[2];
    const float* Uf  = (const float*)d_in[3];
    const float* bf  = (const float*)d_in[4];
    const float* Wb  = (const float*)d_in[5];
    const float* Ub  = (const float*)d_in[6];
    const float* bb  = (const float*)d_in[7];
    float* out = (float*)d_out;

    cudaFuncSetAttribute(xz_gemm_hmma,
                         cudaFuncAttributeMaxDynamicSharedMemorySize, G1_SMEM);
    dim3 ggrid(GSZ / 128, (BSZ * TSZ) / 128, 2);
    xz_gemm_hmma<<<ggrid, 256, G1_SMEM>>>(idx, emb, Wf, bf, Wb, bb);

    // try cluster-16 scan; fall back to proven L2-barrier scan
    cudaFuncSetAttribute(lstm_scan_cluster,
                         cudaFuncAttributeMaxDynamicSharedMemorySize, SMEM_CL);
    cudaFuncSetAttribute(lstm_scan_cluster,
                         cudaFuncAttributeNonPortableClusterSizeAllowed, 1);

    cudaLaunchConfig_t cfg = {};
    cfg.gridDim = dim3(NBLK, 1, 1);
    cfg.blockDim = dim3(256, 1, 1);
    cfg.dynamicSmemBytes = SMEM_CL;

    int maxc = 0;
    cudaError_t qerr = cudaOccupancyMaxPotentialClusterSize(
        &maxc, (const void*)lstm_scan_cluster, &cfg);

    if (qerr == cudaSuccess && maxc >= 16) {
        cudaLaunchAttribute attrs[1];
        attrs[0].id = cudaLaunchAttributeClusterDimension;
        attrs[0].val.clusterDim.x = 16;
        attrs[0].val.clusterDim.y = 1;
        attrs[0].val.clusterDim.z = 1;
        cfg.attrs = attrs;
        cfg.numAttrs = 1;
        cudaLaunchKernelEx(&cfg, lstm_scan_cluster, idx, Uf, Ub, out);
    } else {
        reset_bar_kernel<<<1, 256>>>();
        cudaFuncSetAttribute(lstm_scan_hmma,
                             cudaFuncAttributeMaxDynamicSharedMemorySize, SMEM_FB);
        lstm_scan_hmma<<<NBLK, 256, SMEM_FB>>>(idx, Uf, Ub, out);
    }
}